// round 8
// baseline (speedup 1.0000x reference)
#include <cuda_runtime.h>
#include <cuda_fp16.h>
#include <cuda_bf16.h>
#include <cstdint>

#define N_NODES 100000
#define HEADS   8
#define UNROLL  4
#define MAXE    3200000

// Per-(node, head) sum of exp(e). 3.2 MB.
__device__ float g_sums[N_NODES * HEADS];
// fp16 exp(e) intermediate: 3.2M edges * 8 halves = 51.2 MB (mostly L2-resident).
__device__ __align__(128) __half g_ex[MAXE * HEADS];

__device__ __forceinline__ uint32_t h2_as_u32(__half2 h) {
    return *reinterpret_cast<uint32_t*>(&h);
}
__device__ __forceinline__ __half2 u32_as_h2(uint32_t u) {
    return *reinterpret_cast<__half2*>(&u);
}

__global__ void zero_sums_kernel(int n4) {
    int i = blockIdx.x * blockDim.x + threadIdx.x;
    if (i < n4) reinterpret_cast<float4*>(g_sums)[i] = make_float4(0.f, 0.f, 0.f, 0.f);
}

__device__ __forceinline__ void exp8(float4& a, float4& b) {
    a.x = __expf(a.x); a.y = __expf(a.y); a.z = __expf(a.z); a.w = __expf(a.w);
    b.x = __expf(b.x); b.y = __expf(b.y); b.z = __expf(b.z); b.w = __expf(b.w);
}

// 256-bit streaming load (read-once input).
__device__ __forceinline__ void ld256_cs(const float* p, float4& a, float4& b) {
    uint32_t r0, r1, r2, r3, r4, r5, r6, r7;
    asm volatile("ld.global.cs.v8.b32 {%0,%1,%2,%3,%4,%5,%6,%7}, [%8];"
                 : "=r"(r0), "=r"(r1), "=r"(r2), "=r"(r3),
                   "=r"(r4), "=r"(r5), "=r"(r6), "=r"(r7)
                 : "l"(p));
    a.x = __uint_as_float(r0); a.y = __uint_as_float(r1);
    a.z = __uint_as_float(r2); a.w = __uint_as_float(r3);
    b.x = __uint_as_float(r4); b.y = __uint_as_float(r5);
    b.z = __uint_as_float(r6); b.w = __uint_as_float(r7);
}

// 256-bit store with L2 evict_first (streaming output, don't displace scratch).
__device__ __forceinline__ void st256_evict_first(float* p, float4 a, float4 b) {
    asm volatile("st.global.L2::evict_first.v8.b32 [%0], {%1,%2,%3,%4,%5,%6,%7,%8};"
                 :: "l"(p),
                    "r"(__float_as_uint(a.x)), "r"(__float_as_uint(a.y)),
                    "r"(__float_as_uint(a.z)), "r"(__float_as_uint(a.w)),
                    "r"(__float_as_uint(b.x)), "r"(__float_as_uint(b.y)),
                    "r"(__float_as_uint(b.z)), "r"(__float_as_uint(b.w))
                 : "memory");
}

// Pass 1: ex = exp(e); RED into g_sums[dst] (fp32); store ex as fp16x4 scratch.
__global__ void scatter_sum_kernel(const float* __restrict__ e,
                                   const int* __restrict__ dst,
                                   int E, int useScratch) {
    int base = blockIdx.x * (blockDim.x * UNROLL) + threadIdx.x;

    int d[UNROLL];
    float4 va[UNROLL], vb[UNROLL];
#pragma unroll
    for (int k = 0; k < UNROLL; k++) {
        int i = base + k * blockDim.x;
        if (i < E) {
            d[k] = __ldcs(dst + i);
            ld256_cs(e + (size_t)i * HEADS, va[k], vb[k]);
        }
    }
#pragma unroll
    for (int k = 0; k < UNROLL; k++) {
        int i = base + k * blockDim.x;
        if (i < E) {
            float4 a = va[k], b = vb[k];
            exp8(a, b);
            float* srow = g_sums + (size_t)d[k] * HEADS;
            asm volatile("red.global.add.v4.f32 [%0], {%1, %2, %3, %4};"
                         :: "l"(srow), "f"(a.x), "f"(a.y), "f"(a.z), "f"(a.w) : "memory");
            asm volatile("red.global.add.v4.f32 [%0], {%1, %2, %3, %4};"
                         :: "l"(srow + 4), "f"(b.x), "f"(b.y), "f"(b.z), "f"(b.w) : "memory");
            if (useScratch) {
                uint4 pk;
                pk.x = h2_as_u32(__floats2half2_rn(a.x, a.y));
                pk.y = h2_as_u32(__floats2half2_rn(a.z, a.w));
                pk.z = h2_as_u32(__floats2half2_rn(b.x, b.y));
                pk.w = h2_as_u32(__floats2half2_rn(b.z, b.w));
                reinterpret_cast<uint4*>(g_ex)[i] = pk;  // default (evict_normal) policy
            }
        }
    }
}

// Pass 2 (fast): out = ex16 / (sums[dst] + eps). Reads only the fp16 scratch
// (L2-resident), then discards the dead scratch lines (no writeback).
__global__ void normalize_fast_kernel(const int* __restrict__ dst,
                                      float* __restrict__ out,
                                      int E) {
    int base = blockIdx.x * (blockDim.x * UNROLL) + threadIdx.x;

    int d[UNROLL];
    uint4 pk[UNROLL];
#pragma unroll
    for (int k = 0; k < UNROLL; k++) {
        int i = base + k * blockDim.x;
        if (i < E) {
            d[k]  = __ldcs(dst + i);
            pk[k] = reinterpret_cast<const uint4*>(g_ex)[i];
        }
    }
    const float eps = 1e-16f;
#pragma unroll
    for (int k = 0; k < UNROLL; k++) {
        int i = base + k * blockDim.x;
        if (i < E) {
            float2 x0 = __half22float2(u32_as_h2(pk[k].x));
            float2 x1 = __half22float2(u32_as_h2(pk[k].y));
            float2 x2 = __half22float2(u32_as_h2(pk[k].z));
            float2 x3 = __half22float2(u32_as_h2(pk[k].w));
            const float4* srow = reinterpret_cast<const float4*>(g_sums + (size_t)d[k] * HEADS);
            float4 s0 = srow[0];
            float4 s1 = srow[1];
            float4 o0, o1;
            o0.x = __fdividef(x0.x, s0.x + eps); o0.y = __fdividef(x0.y, s0.y + eps);
            o0.z = __fdividef(x1.x, s0.z + eps); o0.w = __fdividef(x1.y, s0.w + eps);
            o1.x = __fdividef(x2.x, s1.x + eps); o1.y = __fdividef(x2.y, s1.y + eps);
            o1.z = __fdividef(x3.x, s1.z + eps); o1.w = __fdividef(x3.y, s1.w + eps);
            st256_evict_first(out + (size_t)i * HEADS, o0, o1);
        }
    }
    // Discard consumed scratch lines (each 128B line spans 8 consecutive edges;
    // this warp's loads for those edges completed into registers above).
    if ((threadIdx.x & 7) == 0) {
#pragma unroll
        for (int k = 0; k < UNROLL; k++) {
            int i = base + k * blockDim.x;
            if (i < E) {
                const __half* p = g_ex + (size_t)i * HEADS;
                asm volatile("discard.global.L2 [%0], 128;" :: "l"(p) : "memory");
            }
        }
    }
}

// Pass 2 (fallback, E > MAXE): re-read e and recompute exp.
__global__ void normalize_slow_kernel(const float* __restrict__ e,
                                      const int* __restrict__ dst,
                                      float* __restrict__ out,
                                      int E) {
    int base = blockIdx.x * (blockDim.x * UNROLL) + threadIdx.x;
    int d[UNROLL];
    float4 va[UNROLL], vb[UNROLL];
#pragma unroll
    for (int k = 0; k < UNROLL; k++) {
        int i = base + k * blockDim.x;
        if (i < E) {
            d[k] = __ldcs(dst + i);
            ld256_cs(e + (size_t)i * HEADS, va[k], vb[k]);
        }
    }
    const float eps = 1e-16f;
#pragma unroll
    for (int k = 0; k < UNROLL; k++) {
        int i = base + k * blockDim.x;
        if (i < E) {
            float4 a = va[k], b = vb[k];
            exp8(a, b);
            const float4* srow = reinterpret_cast<const float4*>(g_sums + (size_t)d[k] * HEADS);
            float4 s0 = srow[0];
            float4 s1 = srow[1];
            float4 o0, o1;
            o0.x = __fdividef(a.x, s0.x + eps); o0.y = __fdividef(a.y, s0.y + eps);
            o0.z = __fdividef(a.z, s0.z + eps); o0.w = __fdividef(a.w, s0.w + eps);
            o1.x = __fdividef(b.x, s1.x + eps); o1.y = __fdividef(b.y, s1.y + eps);
            o1.z = __fdividef(b.z, s1.z + eps); o1.w = __fdividef(b.w, s1.w + eps);
            st256_evict_first(out + (size_t)i * HEADS, o0, o1);
        }
    }
}

extern "C" void kernel_launch(void* const* d_in, const int* in_sizes, int n_in,
                              void* d_out, int out_size) {
    const float* e = (const float*)d_in[0];
    const int* edge_index = (const int*)d_in[1];
    int E = in_sizes[0] / HEADS;
    const int* dst = edge_index + (size_t)E;  // edge_index[1]
    float* out = (float*)d_out;

    const int T = 256;
    int perBlock = T * UNROLL;
    int nBlocks = (E + perBlock - 1) / perBlock;
    int useScratch = (E <= MAXE) ? 1 : 0;

    zero_sums_kernel<<<(N_NODES * HEADS / 4 + T - 1) / T, T>>>(N_NODES * HEADS / 4);
    scatter_sum_kernel<<<nBlocks, T>>>(e, dst, E, useScratch);
    if (useScratch)
        normalize_fast_kernel<<<nBlocks, T>>>(dst, out, E);
    else
        normalize_slow_kernel<<<nBlocks, T>>>(e, dst, out, E);
}